// round 5
// baseline (speedup 1.0000x reference)
#include <cuda_runtime.h>
#include <math.h>

#define BATCH 256
#define TLEN  512
#define COUT  320
#define NSUBJ 4
#define EPSBN 1e-5f

// ---------------- scratch (no allocations allowed) ----------------
__device__ float g_bufA[(size_t)BATCH * COUT * TLEN];   // 167.8 MB
__device__ float g_bufB[(size_t)BATCH * COUT * TLEN];   // 167.8 MB
__device__ float g_part1[BATCH * COUT];
__device__ float g_part2[BATCH * COUT];
__device__ float g_scale[NSUBJ * COUT];
__device__ float g_shift[NSUBJ * COUT];

// ---------------- conv1d K=3 SAME, tiled fp32 ----------------
// out[b, co, t] = bias[co] + sum_{ci,k} W[co,ci,k] * X[b,ci,t+k-1]  (+ residual)
#define CO_TILE 64
#define T_TILE  256
#define CI_CHUNK 16
#define XROW (T_TILE + 4)   // 260 floats -> row stride 1040B, multiple of 16B

template<bool ADD_RES>
__global__ __launch_bounds__(256, 2)
void conv3_kernel(const float* __restrict__ X, const float* __restrict__ W,
                  const float* __restrict__ bias, float* __restrict__ out, int Cin)
{
    __shared__ float Ws[CI_CHUNK][3][CO_TILE];   // 12 KB
    __shared__ float Xs[CI_CHUNK][XROW];         // 16.25 KB

    const int tid = threadIdx.x;
    const int tx  = tid & 15;        // t-group
    const int ty  = tid >> 4;        // co-group
    const int b   = blockIdx.z;
    const int co0 = blockIdx.y * CO_TILE;
    const int tb  = blockIdx.x * T_TILE;
    const int co_t = co0 + ty * 4;

    float acc[4][16];
    #pragma unroll
    for (int i = 0; i < 4; i++) {
        float bv = bias[co_t + i];
        #pragma unroll
        for (int u = 0; u < 16; u++) acc[i][u] = bv;
    }

    const float* Xb = X + (size_t)b * Cin * TLEN;

    for (int ci0 = 0; ci0 < Cin; ci0 += CI_CHUNK) {
        // ---- load W chunk: Ws[ci][k][co], zero-pad ci >= Cin ----
        #pragma unroll
        for (int it = 0; it < (CI_CHUNK * 3 * CO_TILE) / 256; it++) {
            int idx = tid + it * 256;
            int co_l = idx / (CI_CHUNK * 3);
            int r    = idx - co_l * (CI_CHUNK * 3);
            int ci_l = r / 3;
            int k    = r - ci_l * 3;
            int ci   = ci0 + ci_l;
            float v = 0.f;
            if (ci < Cin) v = W[((size_t)(co0 + co_l) * Cin + ci) * 3 + k];
            Ws[ci_l][k][co_l] = v;
        }
        // ---- load X chunk with halo (t-1 .. t+T_TILE), zero pad ----
        for (int idx = tid; idx < CI_CHUNK * (T_TILE + 2); idx += 256) {
            int ci_l = idx / (T_TILE + 2);
            int tt   = idx - ci_l * (T_TILE + 2);
            int gt   = tb + tt - 1;
            int ci   = ci0 + ci_l;
            float v = 0.f;
            if (ci < Cin && gt >= 0 && gt < TLEN) v = Xb[(size_t)ci * TLEN + gt];
            Xs[ci_l][tt] = v;
        }
        __syncthreads();

        #pragma unroll 4
        for (int ci = 0; ci < CI_CHUNK; ci++) {
            float4 w0v = *(const float4*)&Ws[ci][0][ty * 4];
            float4 w1v = *(const float4*)&Ws[ci][1][ty * 4];
            float4 w2v = *(const float4*)&Ws[ci][2][ty * 4];
            float wk[3][4];
            wk[0][0]=w0v.x; wk[0][1]=w0v.y; wk[0][2]=w0v.z; wk[0][3]=w0v.w;
            wk[1][0]=w1v.x; wk[1][1]=w1v.y; wk[1][2]=w1v.z; wk[1][3]=w1v.w;
            wk[2][0]=w2v.x; wk[2][1]=w2v.y; wk[2][2]=w2v.z; wk[2][3]=w2v.w;
            #pragma unroll
            for (int g = 0; g < 4; g++) {
                const int tl = g * 64 + tx * 4;         // 16B-aligned smem offset
                float4 va = *(const float4*)&Xs[ci][tl];
                float4 vb = *(const float4*)&Xs[ci][tl + 4];
                float v[6] = {va.x, va.y, va.z, va.w, vb.x, vb.y};
                #pragma unroll
                for (int i = 0; i < 4; i++) {
                    #pragma unroll
                    for (int j = 0; j < 4; j++) {
                        acc[i][g * 4 + j] += wk[0][i] * v[j]
                                           + wk[1][i] * v[j + 1]
                                           + wk[2][i] * v[j + 2];
                    }
                }
            }
        }
        __syncthreads();
    }

    // ---- epilogue: optional residual (Cin == COUT path), float4 stores ----
    float* outb = out + (size_t)b * COUT * TLEN;
    #pragma unroll
    for (int i = 0; i < 4; i++) {
        const int co = co_t + i;
        #pragma unroll
        for (int g = 0; g < 4; g++) {
            const int t0 = tb + g * 64 + tx * 4;
            float4 r = make_float4(acc[i][g * 4 + 0], acc[i][g * 4 + 1],
                                   acc[i][g * 4 + 2], acc[i][g * 4 + 3]);
            if (ADD_RES) {
                float4 rs = *(const float4*)&Xb[(size_t)co * TLEN + t0];
                r.x += rs.x; r.y += rs.y; r.z += rs.z; r.w += rs.w;
            }
            *(float4*)&outb[(size_t)co * TLEN + t0] = r;
        }
    }
}

// ---------------- BN stats stage 1: per-(b,c) sum/sumsq (1 warp / row) ----------------
__global__ void stats_rows_g(const float* __restrict__ x)
{
    const int row  = blockIdx.x * 8 + (threadIdx.x >> 5);   // b*COUT + c
    const int lane = threadIdx.x & 31;
    const float* xr = x + (size_t)row * TLEN;
    float s = 0.f, q = 0.f;
    #pragma unroll
    for (int i = 0; i < 4; i++) {
        float4 v = *(const float4*)&xr[lane * 4 + i * 128];
        s += v.x + v.y + v.z + v.w;
        q += v.x * v.x + v.y * v.y + v.z * v.z + v.w * v.w;
    }
    #pragma unroll
    for (int o = 16; o > 0; o >>= 1) {
        s += __shfl_down_sync(0xffffffffu, s, o);
        q += __shfl_down_sync(0xffffffffu, q, o);
    }
    if (lane == 0) { g_part1[row] = s; g_part2[row] = q; }
}

// ---------------- BN stats stage 2: deterministic (s,c) reduce -> scale/shift ----------------
__global__ void stats_reduce_g(const int* __restrict__ subj,
                               const float* __restrict__ gamma, const float* __restrict__ beta)
{
    const int idx = blockIdx.x * blockDim.x + threadIdx.x;
    if (idx >= NSUBJ * COUT) return;
    const int s = idx / COUT;
    const int c = idx - s * COUT;
    float sum = 0.f, sq = 0.f;
    int nb = 0;
    for (int b = 0; b < BATCH; b++) {
        if (subj[b] == s) { sum += g_part1[b * COUT + c]; sq += g_part2[b * COUT + c]; nb++; }
    }
    float cnt  = fmaxf((float)nb * (float)TLEN, 1.0f);
    float mean = sum / cnt;
    float var  = sq / cnt - mean * mean;
    float sc   = gamma[idx] * rsqrtf(var + EPSBN);
    g_scale[idx] = sc;
    g_shift[idx] = beta[idx] - mean * sc;
}

// ---------------- fused BN-apply + exact-erf GELU, in-place float4 ----------------
__device__ __forceinline__ float gelu_exact(float y) {
    return 0.5f * y * (1.0f + erff(y * 0.70710678118654752440f));
}

__global__ void bn_gelu_kernel(float* __restrict__ x, const int* __restrict__ subj)
{
    const int i  = blockIdx.x * blockDim.x + threadIdx.x;        // float4 index
    const int t4 = TLEN / 4;                                     // 128
    const int c  = (i / t4) % COUT;
    const int b  = i / (t4 * COUT);
    const int s  = subj[b];
    const float sc = g_scale[s * COUT + c];
    const float sh = g_shift[s * COUT + c];
    float4 v = ((const float4*)x)[i];
    v.x = gelu_exact(v.x * sc + sh);
    v.y = gelu_exact(v.y * sc + sh);
    v.z = gelu_exact(v.z * sc + sh);
    v.w = gelu_exact(v.w * sc + sh);
    ((float4*)x)[i] = v;
}

// ---------------- launch ----------------
extern "C" void kernel_launch(void* const* d_in, const int* in_sizes, int n_in,
                              void* d_out, int out_size)
{
    const float* X    = (const float*)d_in[0];
    const int*   subj = (const int*)  d_in[1];
    const float* w0   = (const float*)d_in[2];
    const float* b0   = (const float*)d_in[3];
    const float* w1   = (const float*)d_in[4];
    const float* b1   = (const float*)d_in[5];
    const float* w2   = (const float*)d_in[6];
    const float* b2   = (const float*)d_in[7];
    const float* g0   = (const float*)d_in[8];
    const float* be0  = (const float*)d_in[9];
    const float* g1   = (const float*)d_in[10];
    const float* be1  = (const float*)d_in[11];
    const float* g2   = (const float*)d_in[12];
    const float* be2  = (const float*)d_in[13];
    float* out = (float*)d_out;

    float* bufA; cudaGetSymbolAddress((void**)&bufA, g_bufA);
    float* bufB; cudaGetSymbolAddress((void**)&bufB, g_bufB);

    const dim3 cgrid(TLEN / T_TILE, COUT / CO_TILE, BATCH);   // (2, 5, 256)
    const int rows = BATCH * COUT;
    const int ew_grid = (BATCH * COUT * TLEN / 4) / 256;

    // ---- layer 0: conv0 -> bufA ; bn+gelu in place ----
    conv3_kernel<false><<<cgrid, 256>>>(X, w0, b0, bufA, 271);
    stats_rows_g<<<rows / 8, 256>>>(bufA);
    stats_reduce_g<<<(NSUBJ * COUT + 255) / 256, 256>>>(subj, g0, be0);
    bn_gelu_kernel<<<ew_grid, 256>>>(bufA, subj);

    // ---- layer 1: conv1(y0) + y0 -> bufB ; bn+gelu in place ----
    conv3_kernel<true><<<cgrid, 256>>>(bufA, w1, b1, bufB, COUT);
    stats_rows_g<<<rows / 8, 256>>>(bufB);
    stats_reduce_g<<<(NSUBJ * COUT + 255) / 256, 256>>>(subj, g1, be1);
    bn_gelu_kernel<<<ew_grid, 256>>>(bufB, subj);

    // ---- layer 2: conv2(y1) + y1 -> d_out ; bn+gelu in place ----
    conv3_kernel<true><<<cgrid, 256>>>(bufB, w2, b2, out, COUT);
    stats_rows_g<<<rows / 8, 256>>>(out);
    stats_reduce_g<<<(NSUBJ * COUT + 255) / 256, 256>>>(subj, g2, be2);
    bn_gelu_kernel<<<ew_grid, 256>>>(out, subj);
}

// round 7
// speedup vs baseline: 2.2513x; 2.2513x over previous
#include <cuda_runtime.h>
#include <cuda_bf16.h>
#include <cstdint>
#include <math.h>

#define BATCH 256
#define TLEN  512
#define COUT  320
#define CPAD  320           // padded channel stride for transposed bf16 buffers
#define NSUBJ 4
#define EPSBN 1e-5f

// ================= scratch (no allocations allowed) =================
__device__ float g_bufA[(size_t)BATCH * COUT * TLEN];        // fp32 activations (resid/layer out)
__device__ float g_bufB[(size_t)BATCH * COUT * TLEN];
__device__ __nv_bfloat16 g_hi[(size_t)BATCH * TLEN * CPAD];  // bf16 hi split, [b][t][c]
__device__ __nv_bfloat16 g_lo[(size_t)BATCH * TLEN * CPAD];  // bf16 lo split, [b][t][c]
__device__ __nv_bfloat16 g_wfmt[6 * 384 * 320];              // [(ko*2+split)][co384][ci320]
__device__ float g_part1[BATCH * COUT];
__device__ float g_part2[BATCH * COUT];
__device__ float g_scale[NSUBJ * COUT];
__device__ float g_shift[NSUBJ * COUT];

// ================= mma / ldmatrix helpers (base sm_80+ ISA) =================
__device__ __forceinline__ uint32_t smem_addr(const void* p) {
    return (uint32_t)__cvta_generic_to_shared(p);
}
__device__ __forceinline__ void ldsm_x4(uint32_t* r, uint32_t addr) {
    asm volatile("ldmatrix.sync.aligned.m8n8.x4.shared.b16 {%0,%1,%2,%3}, [%4];"
                 : "=r"(r[0]), "=r"(r[1]), "=r"(r[2]), "=r"(r[3]) : "r"(addr));
}
__device__ __forceinline__ void ldsm_x2(uint32_t* r, uint32_t addr) {
    asm volatile("ldmatrix.sync.aligned.m8n8.x2.shared.b16 {%0,%1}, [%2];"
                 : "=r"(r[0]), "=r"(r[1]) : "r"(addr));
}
__device__ __forceinline__ void mma16816(float* c, const uint32_t* a, const uint32_t* b) {
    asm volatile("mma.sync.aligned.m16n8k16.row.col.f32.bf16.bf16.f32 "
                 "{%0,%1,%2,%3}, {%4,%5,%6,%7}, {%8,%9}, {%0,%1,%2,%3};"
                 : "+f"(c[0]), "+f"(c[1]), "+f"(c[2]), "+f"(c[3])
                 : "r"(a[0]), "r"(a[1]), "r"(a[2]), "r"(a[3]), "r"(b[0]), "r"(b[1]));
}

// ================= conv via warp MMA =================
// out[b,co,t] = bias[co] + sum_{ci,ko} W[co,ci,ko]*X[b,ci,t+ko-1] (+resid)
// A = X^T smem [row=t][16 ci]  (tap shift = +ko rows), B = W smem [co][16 ci].
// 3-product split: (Ahi,Whi) + (Ahi,Wlo) + (Alo,Whi).
__global__ __launch_bounds__(256, 2)
void conv_mma_kernel(const __nv_bfloat16* __restrict__ xhi,
                     const __nv_bfloat16* __restrict__ xlo,
                     const __nv_bfloat16* __restrict__ wf,
                     const float* __restrict__ bias,
                     const float* __restrict__ resid,
                     float* __restrict__ out,
                     int nch)
{
    __shared__ __nv_bfloat16 sX[2][132][16];   // [split][t-row (t0-1..t0+128)][ci]
    __shared__ __nv_bfloat16 sW[6][128][16];   // [(ko*2+split)][co][ci]

    const int tid  = threadIdx.x;
    const int wid  = tid >> 5;
    const int lane = tid & 31;
    const int co_blk = blockIdx.x * 128;       // 0,128,256 (co padded to 384)
    const int t0     = blockIdx.y * 128;       // 0..384
    const int b      = blockIdx.z;

    const int warp_t0  = (wid >> 2) * 64;      // 0 / 64
    const int warp_co0 = (wid & 3) * 32;       // 0,32,64,96

    float acc[4][4][4];
    #pragma unroll
    for (int m = 0; m < 4; m++)
        #pragma unroll
        for (int n = 0; n < 4; n++)
            #pragma unroll
            for (int k = 0; k < 4; k++) acc[m][n][k] = 0.f;

    // precomputed ldsm lane addressing pieces
    const int a_row = lane & 15, a_col = (lane >> 4) * 8;
    const int b_row = lane & 7,  b_col = ((lane >> 3) & 1) * 8;

    for (int ch = 0; ch < nch; ch++) {
        const int c0 = ch * 16;
        // ---- W tiles: 6 x [128co][16ci], 2 uint4 per co row ----
        #pragma unroll 2
        for (int idx = tid; idx < 6 * 128 * 2; idx += 256) {
            const int tile = idx >> 8;
            const int r    = idx & 255;
            const int co   = r >> 1, h = r & 1;
            const uint4 v = *(const uint4*)&wf[((size_t)tile * 384 + co_blk + co) * 320 + c0 + h * 8];
            *(uint4*)&sW[tile][co][h * 8] = v;
        }
        // ---- X^T tiles: 130 rows x 2 splits x 2 halves ----
        #pragma unroll 2
        for (int idx = tid; idx < 130 * 2 * 2; idx += 256) {
            const int sp  = idx / 260;
            const int r2  = idx - sp * 260;
            const int row = r2 >> 1, h = r2 & 1;
            const int t   = t0 - 1 + row;
            uint4 v = make_uint4(0u, 0u, 0u, 0u);
            if (t >= 0 && t < TLEN) {
                const __nv_bfloat16* src = sp ? xlo : xhi;
                v = *(const uint4*)&src[((size_t)b * TLEN + t) * CPAD + c0 + h * 8];
            }
            *(uint4*)&sX[sp][row][h * 8] = v;
        }
        __syncthreads();

        #pragma unroll
        for (int ko = 0; ko < 3; ko++) {
            uint32_t bh[4][2], bl[4][2];
            #pragma unroll
            for (int n = 0; n < 4; n++) {
                ldsm_x2(bh[n], smem_addr(&sW[ko * 2 + 0][warp_co0 + n * 8 + b_row][b_col]));
                ldsm_x2(bl[n], smem_addr(&sW[ko * 2 + 1][warp_co0 + n * 8 + b_row][b_col]));
            }
            uint32_t a[4][4];
            #pragma unroll
            for (int m = 0; m < 4; m++)
                ldsm_x4(a[m], smem_addr(&sX[0][warp_t0 + m * 16 + ko + a_row][a_col]));
            #pragma unroll
            for (int m = 0; m < 4; m++)
                #pragma unroll
                for (int n = 0; n < 4; n++) mma16816(acc[m][n], a[m], bh[n]);
            #pragma unroll
            for (int m = 0; m < 4; m++)
                #pragma unroll
                for (int n = 0; n < 4; n++) mma16816(acc[m][n], a[m], bl[n]);
            #pragma unroll
            for (int m = 0; m < 4; m++)
                ldsm_x4(a[m], smem_addr(&sX[1][warp_t0 + m * 16 + ko + a_row][a_col]));
            #pragma unroll
            for (int m = 0; m < 4; m++)
                #pragma unroll
                for (int n = 0; n < 4; n++) mma16816(acc[m][n], a[m], bh[n]);
        }
        __syncthreads();
    }

    // ---- epilogue: acc -> out[b][co][t] + bias (+resid) ----
    const int t_base = t0 + warp_t0 + (lane >> 2);
    #pragma unroll
    for (int n = 0; n < 4; n++) {
        const int co = co_blk + warp_co0 + n * 8 + ((lane & 3) << 1);
        if (co >= COUT) continue;
        const float bv0 = bias[co], bv1 = bias[co + 1];
        #pragma unroll
        for (int m = 0; m < 4; m++) {
            const int t = t_base + m * 16;
            const size_t a0 = ((size_t)b * COUT + co) * TLEN + t;
            const size_t a1 = a0 + TLEN;
            float v0 = acc[m][n][0] + bv0;
            float v1 = acc[m][n][1] + bv1;
            float v2 = acc[m][n][2] + bv0;
            float v3 = acc[m][n][3] + bv1;
            if (resid) {
                v0 += resid[a0]; v1 += resid[a1];
                v2 += resid[a0 + 8]; v3 += resid[a1 + 8];
            }
            out[a0] = v0; out[a1] = v1;
            out[a0 + 8] = v2; out[a1 + 8] = v3;
        }
    }
}

// ================= weight reformat: [(ko*2+sp)][co384][ci320] bf16 =================
__global__ void wfmt_kernel(const float* __restrict__ W, int Cin)
{
    const int idx = blockIdx.x * blockDim.x + threadIdx.x;
    if (idx >= 6 * 384 * 320) return;
    const int ci = idx % 320;
    const int co = (idx / 320) % 384;
    const int ts = idx / (320 * 384);          // tile = ko*2+sp
    const int ko = ts >> 1, sp = ts & 1;
    float v = 0.f;
    if (co < COUT && ci < Cin) v = W[((size_t)co * Cin + ci) * 3 + ko];
    const __nv_bfloat16 h = __float2bfloat16(v);
    g_wfmt[idx] = (sp == 0) ? h : __float2bfloat16(v - __bfloat162float(h));
}

// ================= input convert: X fp32 [b][271][512] -> hi/lo [b][t][320] =================
__global__ void convert_x_tr_kernel(const float* __restrict__ x, int Cin)
{
    __shared__ __nv_bfloat16 sh[128][33];
    __shared__ __nv_bfloat16 sl[128][33];
    const int tid = threadIdx.x;
    const int b   = blockIdx.y;
    const int c0  = blockIdx.x * 32;

    for (int ts = 0; ts < TLEN; ts += 128) {
        for (int idx = tid; idx < 1024; idx += 256) {
            const int ci = idx >> 5, t4 = idx & 31;
            const int c = c0 + ci;
            float4 v = make_float4(0.f, 0.f, 0.f, 0.f);
            if (c < Cin) v = *(const float4*)&x[((size_t)b * Cin + c) * TLEN + ts + t4 * 4];
            const float f[4] = {v.x, v.y, v.z, v.w};
            #pragma unroll
            for (int j = 0; j < 4; j++) {
                const __nv_bfloat16 h = __float2bfloat16(f[j]);
                sh[t4 * 4 + j][ci] = h;
                sl[t4 * 4 + j][ci] = __float2bfloat16(f[j] - __bfloat162float(h));
            }
        }
        __syncthreads();
        for (int idx = tid; idx < 1024; idx += 256) {
            const int arr = idx >> 9;
            const int rem = idx & 511;
            const int r = rem >> 2, q = rem & 3;
            const __nv_bfloat16* src = arr ? &sl[r][q * 8] : &sh[r][q * 8];
            uint16_t tmp[8];
            #pragma unroll
            for (int j = 0; j < 8; j++) tmp[j] = ((const uint16_t*)src)[j];
            __nv_bfloat16* dst = (arr ? g_lo : g_hi) + ((size_t)b * TLEN + ts + r) * CPAD + c0 + q * 8;
            *(uint4*)dst = *(const uint4*)tmp;
        }
        __syncthreads();
    }
}

// ================= BN stats ==================
__global__ void stats_rows_g(const float* __restrict__ x)
{
    const int row  = blockIdx.x * 8 + (threadIdx.x >> 5);
    const int lane = threadIdx.x & 31;
    const float* xr = x + (size_t)row * TLEN;
    float s = 0.f, q = 0.f;
    #pragma unroll
    for (int i = 0; i < 4; i++) {
        const float4 v = *(const float4*)&xr[lane * 4 + i * 128];
        s += v.x + v.y + v.z + v.w;
        q += v.x * v.x + v.y * v.y + v.z * v.z + v.w * v.w;
    }
    #pragma unroll
    for (int o = 16; o > 0; o >>= 1) {
        s += __shfl_down_sync(0xffffffffu, s, o);
        q += __shfl_down_sync(0xffffffffu, q, o);
    }
    if (lane == 0) { g_part1[row] = s; g_part2[row] = q; }
}

__global__ void stats_reduce_g(const int* __restrict__ subj,
                               const float* __restrict__ gamma, const float* __restrict__ beta)
{
    const int idx = blockIdx.x * blockDim.x + threadIdx.x;
    if (idx >= NSUBJ * COUT) return;
    const int s = idx / COUT;
    const int c = idx - s * COUT;
    float sum = 0.f, sq = 0.f;
    int nb = 0;
    for (int b = 0; b < BATCH; b++) {
        if (subj[b] == s) { sum += g_part1[b * COUT + c]; sq += g_part2[b * COUT + c]; nb++; }
    }
    const float cnt  = fmaxf((float)nb * (float)TLEN, 1.0f);
    const float mean = sum / cnt;
    const float var  = sq / cnt - mean * mean;
    const float sc   = gamma[idx] * rsqrtf(var + EPSBN);
    g_scale[idx] = sc;
    g_shift[idx] = beta[idx] - mean * sc;
}

// ====== BN apply + exact GELU (in place) + transposed hi/lo emit ======
__device__ __forceinline__ float gelu_exact(float y) {
    return 0.5f * y * (1.0f + erff(y * 0.70710678118654752440f));
}

__global__ void bn_gelu_tr_kernel(float* __restrict__ x, const int* __restrict__ subj, int emit)
{
    __shared__ __nv_bfloat16 sh[128][33];
    __shared__ __nv_bfloat16 sl[128][33];
    const int tid = threadIdx.x;
    const int b   = blockIdx.y;
    const int c0  = blockIdx.x * 32;
    const int s   = subj[b];

    for (int ts = 0; ts < TLEN; ts += 128) {
        for (int idx = tid; idx < 1024; idx += 256) {
            const int ci = idx >> 5, t4 = idx & 31;
            const int c = c0 + ci;
            const float sc = g_scale[s * COUT + c];
            const float sv = g_shift[s * COUT + c];
            float* xp = &x[((size_t)b * COUT + c) * TLEN + ts + t4 * 4];
            float4 v = *(const float4*)xp;
            v.x = gelu_exact(v.x * sc + sv);
            v.y = gelu_exact(v.y * sc + sv);
            v.z = gelu_exact(v.z * sc + sv);
            v.w = gelu_exact(v.w * sc + sv);
            *(float4*)xp = v;
            if (emit) {
                const float f[4] = {v.x, v.y, v.z, v.w};
                #pragma unroll
                for (int j = 0; j < 4; j++) {
                    const __nv_bfloat16 h = __float2bfloat16(f[j]);
                    sh[t4 * 4 + j][ci] = h;
                    sl[t4 * 4 + j][ci] = __float2bfloat16(f[j] - __bfloat162float(h));
                }
            }
        }
        __syncthreads();
        if (emit) {
            for (int idx = tid; idx < 1024; idx += 256) {
                const int arr = idx >> 9;
                const int rem = idx & 511;
                const int r = rem >> 2, q = rem & 3;
                const __nv_bfloat16* src = arr ? &sl[r][q * 8] : &sh[r][q * 8];
                uint16_t tmp[8];
                #pragma unroll
                for (int j = 0; j < 8; j++) tmp[j] = ((const uint16_t*)src)[j];
                __nv_bfloat16* dst = (arr ? g_lo : g_hi) + ((size_t)b * TLEN + ts + r) * CPAD + c0 + q * 8;
                *(uint4*)dst = *(const uint4*)tmp;
            }
        }
        __syncthreads();
    }
}

// ================= launch =================
extern "C" void kernel_launch(void* const* d_in, const int* in_sizes, int n_in,
                              void* d_out, int out_size)
{
    const float* X    = (const float*)d_in[0];
    const int*   subj = (const int*)  d_in[1];
    const float* w0   = (const float*)d_in[2];
    const float* b0   = (const float*)d_in[3];
    const float* w1   = (const float*)d_in[4];
    const float* b1   = (const float*)d_in[5];
    const float* w2   = (const float*)d_in[6];
    const float* b2   = (const float*)d_in[7];
    const float* g0   = (const float*)d_in[8];
    const float* be0  = (const float*)d_in[9];
    const float* g1   = (const float*)d_in[10];
    const float* be1  = (const float*)d_in[11];
    const float* g2   = (const float*)d_in[12];
    const float* be2  = (const float*)d_in[13];
    float* out = (float*)d_out;

    float* bufA; cudaGetSymbolAddress((void**)&bufA, g_bufA);
    float* bufB; cudaGetSymbolAddress((void**)&bufB, g_bufB);
    __nv_bfloat16* xhi; cudaGetSymbolAddress((void**)&xhi, g_hi);
    __nv_bfloat16* xlo; cudaGetSymbolAddress((void**)&xlo, g_lo);
    __nv_bfloat16* wf;  cudaGetSymbolAddress((void**)&wf,  g_wfmt);

    const dim3 cgrid(3, 4, BATCH);             // co-tiles x t-tiles x batch
    const dim3 egrid(10, BATCH);               // 32-channel tiles x batch
    const int rows = BATCH * COUT;
    const int wfmt_n = 6 * 384 * 320;

    // ---- layer 0 (Cin=271 -> 17 ci chunks of 16 = 272, W zero-padded) ----
    wfmt_kernel<<<(wfmt_n + 255) / 256, 256>>>(w0, 271);
    convert_x_tr_kernel<<<egrid, 256>>>(X, 271);
    conv_mma_kernel<<<cgrid, 256>>>(xhi, xlo, wf, b0, nullptr, bufA, 17);
    stats_rows_g<<<rows / 8, 256>>>(bufA);
    stats_reduce_g<<<(NSUBJ * COUT + 255) / 256, 256>>>(subj, g0, be0);
    bn_gelu_tr_kernel<<<egrid, 256>>>(bufA, subj, 1);

    // ---- layer 1 ----
    wfmt_kernel<<<(wfmt_n + 255) / 256, 256>>>(w1, COUT);
    conv_mma_kernel<<<cgrid, 256>>>(xhi, xlo, wf, b1, bufA, bufB, 20);
    stats_rows_g<<<rows / 8, 256>>>(bufB);
    stats_reduce_g<<<(NSUBJ * COUT + 255) / 256, 256>>>(subj, g1, be1);
    bn_gelu_tr_kernel<<<egrid, 256>>>(bufB, subj, 1);

    // ---- layer 2 ----
    wfmt_kernel<<<(wfmt_n + 255) / 256, 256>>>(w2, COUT);
    conv_mma_kernel<<<cgrid, 256>>>(xhi, xlo, wf, b2, bufB, out, 20);
    stats_rows_g<<<rows / 8, 256>>>(out);
    stats_reduce_g<<<(NSUBJ * COUT + 255) / 256, 256>>>(subj, g2, be2);
    bn_gelu_tr_kernel<<<egrid, 256>>>(out, subj, 0);
}

// round 8
// speedup vs baseline: 2.7772x; 1.2336x over previous
#include <cuda_runtime.h>
#include <cuda_bf16.h>
#include <cstdint>
#include <math.h>

#define BATCH 256
#define TLEN  512
#define COUT  320
#define CPAD  320           // padded channel stride for transposed bf16 buffers
#define NSUBJ 4
#define EPSBN 1e-5f

// ================= scratch (no allocations allowed) =================
__device__ float g_bufA[(size_t)BATCH * COUT * TLEN];
__device__ float g_bufB[(size_t)BATCH * COUT * TLEN];
__device__ __nv_bfloat16 g_hi[(size_t)BATCH * TLEN * CPAD];  // [b][t][c] hi split
__device__ __nv_bfloat16 g_lo[(size_t)BATCH * TLEN * CPAD];  // [b][t][c] lo split
__device__ __nv_bfloat16 g_wfmt[6 * 320 * 320];              // [(ko*2+sp)][co][ci]
__device__ float g_part1[BATCH * COUT];
__device__ float g_part2[BATCH * COUT];
__device__ float g_scale[NSUBJ * COUT];
__device__ float g_shift[NSUBJ * COUT];

// ================= mma / ldmatrix / cp.async helpers =================
__device__ __forceinline__ uint32_t smem_addr(const void* p) {
    return (uint32_t)__cvta_generic_to_shared(p);
}
__device__ __forceinline__ void ldsm_x4(uint32_t* r, uint32_t addr) {
    asm volatile("ldmatrix.sync.aligned.m8n8.x4.shared.b16 {%0,%1,%2,%3}, [%4];"
                 : "=r"(r[0]), "=r"(r[1]), "=r"(r[2]), "=r"(r[3]) : "r"(addr));
}
__device__ __forceinline__ void ldsm_x2(uint32_t* r, uint32_t addr) {
    asm volatile("ldmatrix.sync.aligned.m8n8.x2.shared.b16 {%0,%1}, [%2];"
                 : "=r"(r[0]), "=r"(r[1]) : "r"(addr));
}
__device__ __forceinline__ void mma16816(float* c, const uint32_t* a, const uint32_t* b) {
    asm volatile("mma.sync.aligned.m16n8k16.row.col.f32.bf16.bf16.f32 "
                 "{%0,%1,%2,%3}, {%4,%5,%6,%7}, {%8,%9}, {%0,%1,%2,%3};"
                 : "+f"(c[0]), "+f"(c[1]), "+f"(c[2]), "+f"(c[3])
                 : "r"(a[0]), "r"(a[1]), "r"(a[2]), "r"(a[3]), "r"(b[0]), "r"(b[1]));
}
__device__ __forceinline__ void cp16(uint32_t dst, const void* src) {
    asm volatile("cp.async.cg.shared.global [%0], [%1], 16;" :: "r"(dst), "l"(src));
}
__device__ __forceinline__ void cp16z(uint32_t dst, const void* src, int sz) {
    asm volatile("cp.async.cg.shared.global [%0], [%1], 16, %2;" :: "r"(dst), "l"(src), "r"(sz));
}
#define CP_COMMIT() asm volatile("cp.async.commit_group;")
#define CP_WAIT(n)  asm volatile("cp.async.wait_group %0;" :: "n"(n))

// ================= conv via warp MMA, double-buffered =================
// out[b,co,t] = bias[co] + sum_{ci,ko} W[co,ci,ko]*X[b,ci,t+ko-1] (+resid)
// A = X^T smem [row=t][ci] (tap shift = +ko rows), B = W smem [co][ci].
// 3 products: (Ahi,Whi) + (Ahi,Wlo) + (Alo,Whi).
// smem row stride 24 bf16 (48B) -> ldmatrix rows hit distinct bank groups.
template<int NCOW>
__global__ __launch_bounds__(256, 2)
void conv_mma_kernel(const __nv_bfloat16* __restrict__ xhi,
                     const __nv_bfloat16* __restrict__ xlo,
                     const __nv_bfloat16* __restrict__ wf,
                     const float* __restrict__ bias,
                     const float* __restrict__ resid,
                     float* __restrict__ out,
                     int nch, int co_base0)
{
    constexpr int CO_TILE = NCOW * 32;
    constexpr int XS      = 24;                 // bf16 stride per smem row
    constexpr int XROWS   = 132;
    constexpr int XSTAGE  = 2 * XROWS * XS;     // bf16 per stage (2 splits)
    constexpr int WSTAGE  = 6 * CO_TILE * XS;

    extern __shared__ __nv_bfloat16 smem[];
    __nv_bfloat16* sX = smem;                   // [2][2][XROWS][XS]
    __nv_bfloat16* sW = smem + 2 * XSTAGE;      // [2][6][CO_TILE][XS]

    const int tid  = threadIdx.x;
    const int wid  = tid >> 5;
    const int lane = tid & 31;
    const int co_blk = co_base0 + blockIdx.x * CO_TILE;
    const int t0     = blockIdx.y * 128;
    const int b      = blockIdx.z;

    const int warp_t0  = (wid / NCOW) * (16 * NCOW);
    const int warp_co0 = (wid % NCOW) * 32;

    float acc[NCOW][4][4];
    #pragma unroll
    for (int m = 0; m < NCOW; m++)
        #pragma unroll
        for (int n = 0; n < 4; n++)
            #pragma unroll
            for (int k = 0; k < 4; k++) acc[m][n][k] = 0.f;

    const int a_row = lane & 15, a_col = (lane >> 4) * 8;
    const int b_row = lane & 7,  b_col = ((lane >> 3) & 1) * 8;

    auto load_chunk = [&](int ch, int st) {
        const int c0 = ch * 16;
        for (int idx = tid; idx < 520; idx += 256) {
            const int sp  = idx / 260;
            const int r2  = idx - sp * 260;
            const int row = r2 >> 1, h = r2 & 1;
            const int t   = t0 - 1 + row;
            const int tc  = t < 0 ? 0 : (t > TLEN - 1 ? TLEN - 1 : t);
            const __nv_bfloat16* src = (sp ? xlo : xhi) +
                ((size_t)b * TLEN + tc) * CPAD + c0 + h * 8;
            const uint32_t dst = smem_addr(&sX[st * XSTAGE + sp * (XROWS * XS) + row * XS + h * 8]);
            cp16z(dst, src, (t >= 0 && t < TLEN) ? 16 : 0);
        }
        for (int idx = tid; idx < 6 * CO_TILE * 2; idx += 256) {
            const int tile = idx / (CO_TILE * 2);
            const int r    = idx - tile * (CO_TILE * 2);
            const int co   = r >> 1, h = r & 1;
            const __nv_bfloat16* src = wf + ((size_t)tile * 320 + co_blk + co) * 320 + c0 + h * 8;
            const uint32_t dst = smem_addr(&sW[st * WSTAGE + tile * (CO_TILE * XS) + co * XS + h * 8]);
            cp16(dst, src);
        }
        CP_COMMIT();
    };

    load_chunk(0, 0);

    for (int ch = 0; ch < nch; ch++) {
        const int st = ch & 1;
        if (ch + 1 < nch) { load_chunk(ch + 1, st ^ 1); CP_WAIT(1); }
        else              { CP_WAIT(0); }
        __syncthreads();

        const uint32_t xb0 = smem_addr(&sX[st * XSTAGE]);
        const uint32_t xb1 = smem_addr(&sX[st * XSTAGE + XROWS * XS]);
        const uint32_t wb  = smem_addr(&sW[st * WSTAGE]);

        #pragma unroll
        for (int ko = 0; ko < 3; ko++) {
            uint32_t bh[4][2], bl[4][2];
            #pragma unroll
            for (int n = 0; n < 4; n++) {
                const uint32_t wrow = (uint32_t)((warp_co0 + n * 8 + b_row) * XS + b_col) * 2;
                ldsm_x2(bh[n], wb + (uint32_t)((ko * 2 + 0) * CO_TILE * XS) * 2 + wrow);
                ldsm_x2(bl[n], wb + (uint32_t)((ko * 2 + 1) * CO_TILE * XS) * 2 + wrow);
            }
            uint32_t a[NCOW][4];
            #pragma unroll
            for (int m = 0; m < NCOW; m++)
                ldsm_x4(a[m], xb0 + (uint32_t)((warp_t0 + m * 16 + ko + a_row) * XS + a_col) * 2);
            #pragma unroll
            for (int m = 0; m < NCOW; m++)
                #pragma unroll
                for (int n = 0; n < 4; n++) mma16816(acc[m][n], a[m], bh[n]);
            #pragma unroll
            for (int m = 0; m < NCOW; m++)
                #pragma unroll
                for (int n = 0; n < 4; n++) mma16816(acc[m][n], a[m], bl[n]);
            #pragma unroll
            for (int m = 0; m < NCOW; m++)
                ldsm_x4(a[m], xb1 + (uint32_t)((warp_t0 + m * 16 + ko + a_row) * XS + a_col) * 2);
            #pragma unroll
            for (int m = 0; m < NCOW; m++)
                #pragma unroll
                for (int n = 0; n < 4; n++) mma16816(acc[m][n], a[m], bh[n]);
        }
        __syncthreads();
    }

    // ---- epilogue ----
    const int t_base = t0 + warp_t0 + (lane >> 2);
    #pragma unroll
    for (int n = 0; n < 4; n++) {
        const int co = co_blk + warp_co0 + n * 8 + ((lane & 3) << 1);
        const float bv0 = bias[co], bv1 = bias[co + 1];
        #pragma unroll
        for (int m = 0; m < NCOW; m++) {
            const int t = t_base + m * 16;
            const size_t a0 = ((size_t)b * COUT + co) * TLEN + t;
            const size_t a1 = a0 + TLEN;
            float v0 = acc[m][n][0] + bv0;
            float v1 = acc[m][n][1] + bv1;
            float v2 = acc[m][n][2] + bv0;
            float v3 = acc[m][n][3] + bv1;
            if (resid) {
                v0 += resid[a0]; v1 += resid[a1];
                v2 += resid[a0 + 8]; v3 += resid[a1 + 8];
            }
            out[a0] = v0; out[a1] = v1;
            out[a0 + 8] = v2; out[a1 + 8] = v3;
        }
    }
}

// ================= weight reformat: [(ko*2+sp)][co320][ci320] bf16 =================
__global__ void wfmt_kernel(const float* __restrict__ W, int Cin)
{
    const int idx = blockIdx.x * blockDim.x + threadIdx.x;
    if (idx >= 6 * 320 * 320) return;
    const int ci = idx % 320;
    const int co = (idx / 320) % 320;
    const int ts = idx / (320 * 320);
    const int ko = ts >> 1, sp = ts & 1;
    float v = 0.f;
    if (ci < Cin) v = W[((size_t)co * Cin + ci) * 3 + ko];
    const __nv_bfloat16 h = __float2bfloat16(v);
    g_wfmt[idx] = (sp == 0) ? h : __float2bfloat16(v - __bfloat162float(h));
}

// ================= input convert: X fp32 [b][Cin][512] -> hi/lo [b][t][320] =================
__global__ void convert_x_tr_kernel(const float* __restrict__ x, int Cin)
{
    __shared__ __nv_bfloat16 sh[128][33];
    __shared__ __nv_bfloat16 sl[128][33];
    const int tid = threadIdx.x;
    const int b   = blockIdx.y;
    const int c0  = blockIdx.x * 32;

    for (int ts = 0; ts < TLEN; ts += 128) {
        for (int idx = tid; idx < 1024; idx += 256) {
            const int ci = idx >> 5, t4 = idx & 31;
            const int c = c0 + ci;
            float4 v = make_float4(0.f, 0.f, 0.f, 0.f);
            if (c < Cin) v = *(const float4*)&x[((size_t)b * Cin + c) * TLEN + ts + t4 * 4];
            const float f[4] = {v.x, v.y, v.z, v.w};
            #pragma unroll
            for (int j = 0; j < 4; j++) {
                const __nv_bfloat16 h = __float2bfloat16(f[j]);
                sh[t4 * 4 + j][ci] = h;
                sl[t4 * 4 + j][ci] = __float2bfloat16(f[j] - __bfloat162float(h));
            }
        }
        __syncthreads();
        for (int idx = tid; idx < 1024; idx += 256) {
            const int arr = idx >> 9;
            const int rem = idx & 511;
            const int r = rem >> 2, q = rem & 3;
            const __nv_bfloat16* src = arr ? &sl[r][q * 8] : &sh[r][q * 8];
            uint16_t tmp[8];
            #pragma unroll
            for (int j = 0; j < 8; j++) tmp[j] = ((const uint16_t*)src)[j];
            __nv_bfloat16* dst = (arr ? g_lo : g_hi) + ((size_t)b * TLEN + ts + r) * CPAD + c0 + q * 8;
            *(uint4*)dst = *(const uint4*)tmp;
        }
        __syncthreads();
    }
}

// ================= BN stats ==================
__global__ void stats_rows_g(const float* __restrict__ x)
{
    const int row  = blockIdx.x * 8 + (threadIdx.x >> 5);
    const int lane = threadIdx.x & 31;
    const float* xr = x + (size_t)row * TLEN;
    float s = 0.f, q = 0.f;
    #pragma unroll
    for (int i = 0; i < 4; i++) {
        const float4 v = *(const float4*)&xr[lane * 4 + i * 128];
        s += v.x + v.y + v.z + v.w;
        q += v.x * v.x + v.y * v.y + v.z * v.z + v.w * v.w;
    }
    #pragma unroll
    for (int o = 16; o > 0; o >>= 1) {
        s += __shfl_down_sync(0xffffffffu, s, o);
        q += __shfl_down_sync(0xffffffffu, q, o);
    }
    if (lane == 0) { g_part1[row] = s; g_part2[row] = q; }
}

__global__ void stats_reduce_g(const int* __restrict__ subj,
                               const float* __restrict__ gamma, const float* __restrict__ beta)
{
    const int idx = blockIdx.x * blockDim.x + threadIdx.x;
    if (idx >= NSUBJ * COUT) return;
    const int s = idx / COUT;
    const int c = idx - s * COUT;
    float sum = 0.f, sq = 0.f;
    int nb = 0;
    for (int b = 0; b < BATCH; b++) {
        if (subj[b] == s) { sum += g_part1[b * COUT + c]; sq += g_part2[b * COUT + c]; nb++; }
    }
    const float cnt  = fmaxf((float)nb * (float)TLEN, 1.0f);
    const float mean = sum / cnt;
    const float var  = sq / cnt - mean * mean;
    const float sc   = gamma[idx] * rsqrtf(var + EPSBN);
    g_scale[idx] = sc;
    g_shift[idx] = beta[idx] - mean * sc;
}

// ====== BN apply + exact GELU (in place) + transposed hi/lo emit ======
__device__ __forceinline__ float gelu_exact(float y) {
    return 0.5f * y * (1.0f + erff(y * 0.70710678118654752440f));
}

__global__ void bn_gelu_tr_kernel(float* __restrict__ x, const int* __restrict__ subj, int emit)
{
    __shared__ __nv_bfloat16 sh[128][33];
    __shared__ __nv_bfloat16 sl[128][33];
    const int tid = threadIdx.x;
    const int b   = blockIdx.y;
    const int c0  = blockIdx.x * 32;
    const int s   = subj[b];

    for (int ts = 0; ts < TLEN; ts += 128) {
        for (int idx = tid; idx < 1024; idx += 256) {
            const int ci = idx >> 5, t4 = idx & 31;
            const int c = c0 + ci;
            const float sc = g_scale[s * COUT + c];
            const float sv = g_shift[s * COUT + c];
            float* xp = &x[((size_t)b * COUT + c) * TLEN + ts + t4 * 4];
            float4 v = *(const float4*)xp;
            v.x = gelu_exact(v.x * sc + sv);
            v.y = gelu_exact(v.y * sc + sv);
            v.z = gelu_exact(v.z * sc + sv);
            v.w = gelu_exact(v.w * sc + sv);
            *(float4*)xp = v;
            if (emit) {
                const float f[4] = {v.x, v.y, v.z, v.w};
                #pragma unroll
                for (int j = 0; j < 4; j++) {
                    const __nv_bfloat16 h = __float2bfloat16(f[j]);
                    sh[t4 * 4 + j][ci] = h;
                    sl[t4 * 4 + j][ci] = __float2bfloat16(f[j] - __bfloat162float(h));
                }
            }
        }
        __syncthreads();
        if (emit) {
            for (int idx = tid; idx < 1024; idx += 256) {
                const int arr = idx >> 9;
                const int rem = idx & 511;
                const int r = rem >> 2, q = rem & 3;
                const __nv_bfloat16* src = arr ? &sl[r][q * 8] : &sh[r][q * 8];
                uint16_t tmp[8];
                #pragma unroll
                for (int j = 0; j < 8; j++) tmp[j] = ((const uint16_t*)src)[j];
                __nv_bfloat16* dst = (arr ? g_lo : g_hi) + ((size_t)b * TLEN + ts + r) * CPAD + c0 + q * 8;
                *(uint4*)dst = *(const uint4*)tmp;
            }
        }
        __syncthreads();
    }
}

// ================= launch =================
extern "C" void kernel_launch(void* const* d_in, const int* in_sizes, int n_in,
                              void* d_out, int out_size)
{
    const float* X    = (const float*)d_in[0];
    const int*   subj = (const int*)  d_in[1];
    const float* w0   = (const float*)d_in[2];
    const float* b0   = (const float*)d_in[3];
    const float* w1   = (const float*)d_in[4];
    const float* b1   = (const float*)d_in[5];
    const float* w2   = (const float*)d_in[6];
    const float* b2   = (const float*)d_in[7];
    const float* g0   = (const float*)d_in[8];
    const float* be0  = (const float*)d_in[9];
    const float* g1   = (const float*)d_in[10];
    const float* be1  = (const float*)d_in[11];
    const float* g2   = (const float*)d_in[12];
    const float* be2  = (const float*)d_in[13];
    float* out = (float*)d_out;

    float* bufA; cudaGetSymbolAddress((void**)&bufA, g_bufA);
    float* bufB; cudaGetSymbolAddress((void**)&bufB, g_bufB);
    __nv_bfloat16* xhi; cudaGetSymbolAddress((void**)&xhi, g_hi);
    __nv_bfloat16* xlo; cudaGetSymbolAddress((void**)&xlo, g_lo);
    __nv_bfloat16* wf;  cudaGetSymbolAddress((void**)&wf,  g_wfmt);

    // dynamic smem: (2*2*132*24 + 2*6*CO_TILE*24) bf16
    const int smA = (2 * 2 * 132 * 24 + 2 * 6 * 128 * 24) * 2;   // 99072 B
    const int smB = (2 * 2 * 132 * 24 + 2 * 6 * 64 * 24) * 2;    // 62208 B
    cudaFuncSetAttribute(conv_mma_kernel<4>, cudaFuncAttributeMaxDynamicSharedMemorySize, smA);
    cudaFuncSetAttribute(conv_mma_kernel<2>, cudaFuncAttributeMaxDynamicSharedMemorySize, smB);

    const dim3 gridA(2, 4, BATCH);   // co tiles 0,128
    const dim3 gridB(1, 4, BATCH);   // co tile 256..319
    const dim3 egrid(10, BATCH);
    const int rows = BATCH * COUT;
    const int wfmt_n = 6 * 320 * 320;

    // ---- layer 0 (Cin=271 -> 17 ci chunks; buffers zero-padded) ----
    wfmt_kernel<<<(wfmt_n + 255) / 256, 256>>>(w0, 271);
    convert_x_tr_kernel<<<egrid, 256>>>(X, 271);
    conv_mma_kernel<4><<<gridA, 256, smA>>>(xhi, xlo, wf, b0, nullptr, bufA, 17, 0);
    conv_mma_kernel<2><<<gridB, 256, smB>>>(xhi, xlo, wf, b0, nullptr, bufA, 17, 256);
    stats_rows_g<<<rows / 8, 256>>>(bufA);
    stats_reduce_g<<<(NSUBJ * COUT + 255) / 256, 256>>>(subj, g0, be0);
    bn_gelu_tr_kernel<<<egrid, 256>>>(bufA, subj, 1);

    // ---- layer 1 ----
    wfmt_kernel<<<(wfmt_n + 255) / 256, 256>>>(w1, COUT);
    conv_mma_kernel<4><<<gridA, 256, smA>>>(xhi, xlo, wf, b1, bufA, bufB, 20, 0);
    conv_mma_kernel<2><<<gridB, 256, smB>>>(xhi, xlo, wf, b1, bufA, bufB, 20, 256);
    stats_rows_g<<<rows / 8, 256>>>(bufB);
    stats_reduce_g<<<(NSUBJ * COUT + 255) / 256, 256>>>(subj, g1, be1);
    bn_gelu_tr_kernel<<<egrid, 256>>>(bufB, subj, 1);

    // ---- layer 2 ----
    wfmt_kernel<<<(wfmt_n + 255) / 256, 256>>>(w2, COUT);
    conv_mma_kernel<4><<<gridA, 256, smA>>>(xhi, xlo, wf, b2, bufB, out, 20, 0);
    conv_mma_kernel<2><<<gridB, 256, smB>>>(xhi, xlo, wf, b2, bufB, out, 20, 256);
    stats_rows_g<<<rows / 8, 256>>>(out);
    stats_reduce_g<<<(NSUBJ * COUT + 255) / 256, 256>>>(subj, g2, be2);
    bn_gelu_tr_kernel<<<egrid, 256>>>(out, subj, 0);
}

// round 9
// speedup vs baseline: 3.1535x; 1.1355x over previous
#include <cuda_runtime.h>
#include <cuda_bf16.h>
#include <cstdint>
#include <math.h>

#define BATCH 256
#define TLEN  512
#define COUT  320
#define CPAD  320
#define NSUBJ 4
#define EPSBN 1e-5f

// ================= scratch (no allocations allowed) =================
__device__ float g_bufA[(size_t)BATCH * COUT * TLEN];
__device__ float g_bufB[(size_t)BATCH * COUT * TLEN];
__device__ __nv_bfloat16 g_hi[(size_t)BATCH * TLEN * CPAD];  // [b][t][c] hi split
__device__ __nv_bfloat16 g_lo[(size_t)BATCH * TLEN * CPAD];  // [b][t][c] lo split
__device__ __nv_bfloat16 g_wfmt[3 * 6 * 320 * 320];          // [layer][(ko*2+sp)][co][ci]
__device__ float g_part1[BATCH * COUT];
__device__ float g_part2[BATCH * COUT];
__device__ float g_scale[NSUBJ * COUT];
__device__ float g_shift[NSUBJ * COUT];

// ================= mma / ldmatrix / cp.async helpers =================
__device__ __forceinline__ uint32_t smem_addr(const void* p) {
    return (uint32_t)__cvta_generic_to_shared(p);
}
__device__ __forceinline__ void ldsm_x4(uint32_t* r, uint32_t addr) {
    asm volatile("ldmatrix.sync.aligned.m8n8.x4.shared.b16 {%0,%1,%2,%3}, [%4];"
                 : "=r"(r[0]), "=r"(r[1]), "=r"(r[2]), "=r"(r[3]) : "r"(addr));
}
__device__ __forceinline__ void ldsm_x2(uint32_t* r, uint32_t addr) {
    asm volatile("ldmatrix.sync.aligned.m8n8.x2.shared.b16 {%0,%1}, [%2];"
                 : "=r"(r[0]), "=r"(r[1]) : "r"(addr));
}
__device__ __forceinline__ void mma16816(float* c, const uint32_t* a, const uint32_t* b) {
    asm volatile("mma.sync.aligned.m16n8k16.row.col.f32.bf16.bf16.f32 "
                 "{%0,%1,%2,%3}, {%4,%5,%6,%7}, {%8,%9}, {%0,%1,%2,%3};"
                 : "+f"(c[0]), "+f"(c[1]), "+f"(c[2]), "+f"(c[3])
                 : "r"(a[0]), "r"(a[1]), "r"(a[2]), "r"(a[3]), "r"(b[0]), "r"(b[1]));
}
__device__ __forceinline__ void cp16(uint32_t dst, const void* src) {
    asm volatile("cp.async.cg.shared.global [%0], [%1], 16;" :: "r"(dst), "l"(src));
}
__device__ __forceinline__ void cp16z(uint32_t dst, const void* src, int sz) {
    asm volatile("cp.async.cg.shared.global [%0], [%1], 16, %2;" :: "r"(dst), "l"(src), "r"(sz));
}
#define CP_COMMIT() asm volatile("cp.async.commit_group;")
#define CP_WAIT(n)  asm volatile("cp.async.wait_group %0;" :: "n"(n))

// ================= conv via warp MMA, double-buffered, CO_TILE=64 =================
// out[b,co,t] = bias[co] + sum_{ci,ko} W[co,ci,ko]*X[b,ci,t+ko-1] (+resid)
// A = X^T smem [row=t][ci] (tap shift = +ko rows), B = W smem [co][ci].
// 3 products: (Ahi,Whi) + (Ahi,Wlo) + (Alo,Whi).
// Warps: 4 t-warps x 2 co-warps. 3 CTAs/SM (regs<=84, smem 62KB).
#define XS    24           // bf16 stride per smem row (48B -> conflict-free ldsm)
#define XROWS 132
#define XSTAGE (2 * XROWS * XS)      // bf16 per stage (2 splits)
#define WSTAGE (6 * 64 * XS)
#define CONV_SMEM ((2 * XSTAGE + 2 * WSTAGE) * 2)   // 62208 B

__global__ __launch_bounds__(256, 3)
void conv_mma_kernel(const __nv_bfloat16* __restrict__ xhi,
                     const __nv_bfloat16* __restrict__ xlo,
                     const __nv_bfloat16* __restrict__ wf,
                     const float* __restrict__ bias,
                     const float* __restrict__ resid,
                     float* __restrict__ out,
                     int nch)
{
    extern __shared__ __nv_bfloat16 smem[];
    __nv_bfloat16* sX = smem;                   // [2 stage][2 split][XROWS][XS]
    __nv_bfloat16* sW = smem + 2 * XSTAGE;      // [2 stage][6][64][XS]

    const int tid  = threadIdx.x;
    const int wid  = tid >> 5;
    const int lane = tid & 31;
    const int co_blk = blockIdx.x * 64;
    const int t0     = blockIdx.y * 128;
    const int b      = blockIdx.z;

    const int warp_t0  = (wid >> 1) * 32;       // 0,32,64,96
    const int warp_co0 = (wid & 1) * 32;        // 0,32

    float acc[2][4][4];
    #pragma unroll
    for (int m = 0; m < 2; m++)
        #pragma unroll
        for (int n = 0; n < 4; n++)
            #pragma unroll
            for (int k = 0; k < 4; k++) acc[m][n][k] = 0.f;

    const int a_row = lane & 15, a_col = (lane >> 4) * 8;
    const int b_row = lane & 7,  b_col = ((lane >> 3) & 1) * 8;

    auto load_chunk = [&](int ch, int st) {
        const int c0 = ch * 16;
        for (int idx = tid; idx < 520; idx += 256) {
            const int sp  = idx / 260;
            const int r2  = idx - sp * 260;
            const int row = r2 >> 1, h = r2 & 1;
            const int t   = t0 - 1 + row;
            const int tc  = t < 0 ? 0 : (t > TLEN - 1 ? TLEN - 1 : t);
            const __nv_bfloat16* src = (sp ? xlo : xhi) +
                ((size_t)b * TLEN + tc) * CPAD + c0 + h * 8;
            const uint32_t dst = smem_addr(&sX[st * XSTAGE + sp * (XROWS * XS) + row * XS + h * 8]);
            cp16z(dst, src, (t >= 0 && t < TLEN) ? 16 : 0);
        }
        for (int idx = tid; idx < 6 * 64 * 2; idx += 256) {
            const int tile = idx >> 7;
            const int r    = idx & 127;
            const int co   = r >> 1, h = r & 1;
            const __nv_bfloat16* src = wf + ((size_t)tile * 320 + co_blk + co) * 320 + c0 + h * 8;
            const uint32_t dst = smem_addr(&sW[st * WSTAGE + tile * (64 * XS) + co * XS + h * 8]);
            cp16(dst, src);
        }
        CP_COMMIT();
    };

    load_chunk(0, 0);

    for (int ch = 0; ch < nch; ch++) {
        const int st = ch & 1;
        if (ch + 1 < nch) { load_chunk(ch + 1, st ^ 1); CP_WAIT(1); }
        else              { CP_WAIT(0); }
        __syncthreads();

        const uint32_t xb0 = smem_addr(&sX[st * XSTAGE]);
        const uint32_t xb1 = smem_addr(&sX[st * XSTAGE + XROWS * XS]);
        const uint32_t wb  = smem_addr(&sW[st * WSTAGE]);

        #pragma unroll
        for (int ko = 0; ko < 3; ko++) {
            uint32_t bh[4][2], bl[4][2];
            #pragma unroll
            for (int n = 0; n < 4; n++) {
                const uint32_t wrow = (uint32_t)((warp_co0 + n * 8 + b_row) * XS + b_col) * 2;
                ldsm_x2(bh[n], wb + (uint32_t)((ko * 2 + 0) * 64 * XS) * 2 + wrow);
                ldsm_x2(bl[n], wb + (uint32_t)((ko * 2 + 1) * 64 * XS) * 2 + wrow);
            }
            uint32_t a[2][4];
            #pragma unroll
            for (int m = 0; m < 2; m++)
                ldsm_x4(a[m], xb0 + (uint32_t)((warp_t0 + m * 16 + ko + a_row) * XS + a_col) * 2);
            #pragma unroll
            for (int m = 0; m < 2; m++)
                #pragma unroll
                for (int n = 0; n < 4; n++) mma16816(acc[m][n], a[m], bh[n]);
            #pragma unroll
            for (int m = 0; m < 2; m++)
                #pragma unroll
                for (int n = 0; n < 4; n++) mma16816(acc[m][n], a[m], bl[n]);
            #pragma unroll
            for (int m = 0; m < 2; m++)
                ldsm_x4(a[m], xb1 + (uint32_t)((warp_t0 + m * 16 + ko + a_row) * XS + a_col) * 2);
            #pragma unroll
            for (int m = 0; m < 2; m++)
                #pragma unroll
                for (int n = 0; n < 4; n++) mma16816(acc[m][n], a[m], bh[n]);
        }
        __syncthreads();
    }

    // ---- epilogue via smem transpose: coalesced t-major I/O ----
    float* sO = (float*)smem;                   // [64 co][132 t] = 33792 B
    {
        const int t_l = warp_t0 + (lane >> 2);
        #pragma unroll
        for (int n = 0; n < 4; n++) {
            const int co_l = warp_co0 + n * 8 + ((lane & 3) << 1);
            #pragma unroll
            for (int m = 0; m < 2; m++) {
                const int t = t_l + m * 16;
                sO[co_l * 132 + t]           = acc[m][n][0];
                sO[(co_l + 1) * 132 + t]     = acc[m][n][1];
                sO[co_l * 132 + t + 8]       = acc[m][n][2];
                sO[(co_l + 1) * 132 + t + 8] = acc[m][n][3];
            }
        }
    }
    __syncthreads();
    for (int idx = tid; idx < 64 * 32; idx += 256) {
        const int co = idx >> 5, t4 = idx & 31;
        float4 v = *(const float4*)&sO[co * 132 + t4 * 4];
        const float bv = bias[co_blk + co];
        v.x += bv; v.y += bv; v.z += bv; v.w += bv;
        const size_t adr = ((size_t)b * COUT + co_blk + co) * TLEN + t0 + t4 * 4;
        if (resid) {
            const float4 r = *(const float4*)&resid[adr];
            v.x += r.x; v.y += r.y; v.z += r.z; v.w += r.w;
        }
        *(float4*)&out[adr] = v;
    }
}

// ================= weight reformat: [(ko*2+sp)][co320][ci320] bf16 =================
__global__ void wfmt_kernel(const float* __restrict__ W, int Cin, int layer)
{
    const int idx = blockIdx.x * blockDim.x + threadIdx.x;
    if (idx >= 6 * 320 * 320) return;
    const int ci = idx % 320;
    const int co = (idx / 320) % 320;
    const int ts = idx / (320 * 320);
    const int ko = ts >> 1, sp = ts & 1;
    float v = 0.f;
    if (ci < Cin) v = W[((size_t)co * Cin + ci) * 3 + ko];
    const __nv_bfloat16 h = __float2bfloat16(v);
    g_wfmt[(size_t)layer * 6 * 320 * 320 + idx] =
        (sp == 0) ? h : __float2bfloat16(v - __bfloat162float(h));
}

// ================= input convert: X fp32 [b][Cin][512] -> hi/lo [b][t][320] =================
__global__ void convert_x_tr_kernel(const float* __restrict__ x, int Cin)
{
    __shared__ __nv_bfloat16 sh[128][33];
    __shared__ __nv_bfloat16 sl[128][33];
    const int tid = threadIdx.x;
    const int b   = blockIdx.y;
    const int c0  = blockIdx.x * 32;

    for (int ts = 0; ts < TLEN; ts += 128) {
        for (int idx = tid; idx < 1024; idx += 256) {
            const int ci = idx >> 5, t4 = idx & 31;
            const int c = c0 + ci;
            float4 v = make_float4(0.f, 0.f, 0.f, 0.f);
            if (c < Cin) v = *(const float4*)&x[((size_t)b * Cin + c) * TLEN + ts + t4 * 4];
            const float f[4] = {v.x, v.y, v.z, v.w};
            #pragma unroll
            for (int j = 0; j < 4; j++) {
                const __nv_bfloat16 h = __float2bfloat16(f[j]);
                sh[t4 * 4 + j][ci] = h;
                sl[t4 * 4 + j][ci] = __float2bfloat16(f[j] - __bfloat162float(h));
            }
        }
        __syncthreads();
        for (int idx = tid; idx < 1024; idx += 256) {
            const int arr = idx >> 9;
            const int rem = idx & 511;
            const int r = rem >> 2, q = rem & 3;
            const __nv_bfloat16* src = arr ? &sl[r][q * 8] : &sh[r][q * 8];
            uint16_t tmp[8];
            #pragma unroll
            for (int j = 0; j < 8; j++) tmp[j] = ((const uint16_t*)src)[j];
            __nv_bfloat16* dst = (arr ? g_lo : g_hi) + ((size_t)b * TLEN + ts + r) * CPAD + c0 + q * 8;
            *(uint4*)dst = *(const uint4*)tmp;
        }
        __syncthreads();
    }
}

// ================= BN stats ==================
__global__ void stats_rows_g(const float* __restrict__ x)
{
    const int row  = blockIdx.x * 8 + (threadIdx.x >> 5);
    const int lane = threadIdx.x & 31;
    const float* xr = x + (size_t)row * TLEN;
    float s = 0.f, q = 0.f;
    #pragma unroll
    for (int i = 0; i < 4; i++) {
        const float4 v = *(const float4*)&xr[lane * 4 + i * 128];
        s += v.x + v.y + v.z + v.w;
        q += v.x * v.x + v.y * v.y + v.z * v.z + v.w * v.w;
    }
    #pragma unroll
    for (int o = 16; o > 0; o >>= 1) {
        s += __shfl_down_sync(0xffffffffu, s, o);
        q += __shfl_down_sync(0xffffffffu, q, o);
    }
    if (lane == 0) { g_part1[row] = s; g_part2[row] = q; }
}

__global__ void stats_reduce_g(const int* __restrict__ subj,
                               const float* __restrict__ gamma, const float* __restrict__ beta)
{
    const int idx = blockIdx.x * blockDim.x + threadIdx.x;
    if (idx >= NSUBJ * COUT) return;
    const int s = idx / COUT;
    const int c = idx - s * COUT;
    float sum = 0.f, sq = 0.f;
    int nb = 0;
    for (int b = 0; b < BATCH; b++) {
        if (subj[b] == s) { sum += g_part1[b * COUT + c]; sq += g_part2[b * COUT + c]; nb++; }
    }
    const float cnt  = fmaxf((float)nb * (float)TLEN, 1.0f);
    const float mean = sum / cnt;
    const float var  = sq / cnt - mean * mean;
    const float sc   = gamma[idx] * rsqrtf(var + EPSBN);
    g_scale[idx] = sc;
    g_shift[idx] = beta[idx] - mean * sc;
}

// ====== BN apply + exact GELU (in place) + transposed hi/lo emit ======
__device__ __forceinline__ float gelu_exact(float y) {
    return 0.5f * y * (1.0f + erff(y * 0.70710678118654752440f));
}

__global__ void bn_gelu_tr_kernel(float* __restrict__ x, const int* __restrict__ subj, int emit)
{
    __shared__ __nv_bfloat16 sh[128][33];
    __shared__ __nv_bfloat16 sl[128][33];
    const int tid = threadIdx.x;
    const int b   = blockIdx.y;
    const int c0  = blockIdx.x * 32;
    const int s   = subj[b];

    for (int ts = 0; ts < TLEN; ts += 128) {
        for (int idx = tid; idx < 1024; idx += 256) {
            const int ci = idx >> 5, t4 = idx & 31;
            const int c = c0 + ci;
            const float sc = g_scale[s * COUT + c];
            const float sv = g_shift[s * COUT + c];
            float* xp = &x[((size_t)b * COUT + c) * TLEN + ts + t4 * 4];
            float4 v = *(const float4*)xp;
            v.x = gelu_exact(v.x * sc + sv);
            v.y = gelu_exact(v.y * sc + sv);
            v.z = gelu_exact(v.z * sc + sv);
            v.w = gelu_exact(v.w * sc + sv);
            *(float4*)xp = v;
            if (emit) {
                const float f[4] = {v.x, v.y, v.z, v.w};
                #pragma unroll
                for (int j = 0; j < 4; j++) {
                    const __nv_bfloat16 h = __float2bfloat16(f[j]);
                    sh[t4 * 4 + j][ci] = h;
                    sl[t4 * 4 + j][ci] = __float2bfloat16(f[j] - __bfloat162float(h));
                }
            }
        }
        __syncthreads();
        if (emit) {
            for (int idx = tid; idx < 1024; idx += 256) {
                const int arr = idx >> 9;
                const int rem = idx & 511;
                const int r = rem >> 2, q = rem & 3;
                const __nv_bfloat16* src = arr ? &sl[r][q * 8] : &sh[r][q * 8];
                uint16_t tmp[8];
                #pragma unroll
                for (int j = 0; j < 8; j++) tmp[j] = ((const uint16_t*)src)[j];
                __nv_bfloat16* dst = (arr ? g_lo : g_hi) + ((size_t)b * TLEN + ts + r) * CPAD + c0 + q * 8;
                *(uint4*)dst = *(const uint4*)tmp;
            }
        }
        __syncthreads();
    }
}

// ================= launch =================
extern "C" void kernel_launch(void* const* d_in, const int* in_sizes, int n_in,
                              void* d_out, int out_size)
{
    const float* X    = (const float*)d_in[0];
    const int*   subj = (const int*)  d_in[1];
    const float* w0   = (const float*)d_in[2];
    const float* b0   = (const float*)d_in[3];
    const float* w1   = (const float*)d_in[4];
    const float* b1   = (const float*)d_in[5];
    const float* w2   = (const float*)d_in[6];
    const float* b2   = (const float*)d_in[7];
    const float* g0   = (const float*)d_in[8];
    const float* be0  = (const float*)d_in[9];
    const float* g1   = (const float*)d_in[10];
    const float* be1  = (const float*)d_in[11];
    const float* g2   = (const float*)d_in[12];
    const float* be2  = (const float*)d_in[13];
    float* out = (float*)d_out;

    float* bufA; cudaGetSymbolAddress((void**)&bufA, g_bufA);
    float* bufB; cudaGetSymbolAddress((void**)&bufB, g_bufB);
    __nv_bfloat16* xhi; cudaGetSymbolAddress((void**)&xhi, g_hi);
    __nv_bfloat16* xlo; cudaGetSymbolAddress((void**)&xlo, g_lo);
    __nv_bfloat16* wf;  cudaGetSymbolAddress((void**)&wf,  g_wfmt);
    const size_t wstep = (size_t)6 * 320 * 320;

    cudaFuncSetAttribute(conv_mma_kernel,
                         cudaFuncAttributeMaxDynamicSharedMemorySize, CONV_SMEM);

    const dim3 cgrid(5, 4, BATCH);     // co 64-tiles x t 128-tiles x batch
    const dim3 egrid(10, BATCH);
    const int rows = BATCH * COUT;
    const int wfmt_n = 6 * 320 * 320;

    // ---- weight prep for all layers up front ----
    wfmt_kernel<<<(wfmt_n + 255) / 256, 256>>>(w0, 271, 0);
    wfmt_kernel<<<(wfmt_n + 255) / 256, 256>>>(w1, COUT, 1);
    wfmt_kernel<<<(wfmt_n + 255) / 256, 256>>>(w2, COUT, 2);
    convert_x_tr_kernel<<<egrid, 256>>>(X, 271);

    // ---- layer 0 ----
    conv_mma_kernel<<<cgrid, 256, CONV_SMEM>>>(xhi, xlo, wf, b0, nullptr, bufA, 17);
    stats_rows_g<<<rows / 8, 256>>>(bufA);
    stats_reduce_g<<<(NSUBJ * COUT + 255) / 256, 256>>>(subj, g0, be0);
    bn_gelu_tr_kernel<<<egrid, 256>>>(bufA, subj, 1);

    // ---- layer 1 ----
    conv_mma_kernel<<<cgrid, 256, CONV_SMEM>>>(xhi, xlo, wf + wstep, b1, bufA, bufB, 20);
    stats_rows_g<<<rows / 8, 256>>>(bufB);
    stats_reduce_g<<<(NSUBJ * COUT + 255) / 256, 256>>>(subj, g1, be1);
    bn_gelu_tr_kernel<<<egrid, 256>>>(bufB, subj, 1);

    // ---- layer 2 ----
    conv_mma_kernel<<<cgrid, 256, CONV_SMEM>>>(xhi, xlo, wf + 2 * wstep, b2, bufB, out, 20);
    stats_rows_g<<<rows / 8, 256>>>(out);
    stats_reduce_g<<<(NSUBJ * COUT + 255) / 256, 256>>>(subj, g2, be2);
    bn_gelu_tr_kernel<<<egrid, 256>>>(out, subj, 0);
}